// round 14
// baseline (speedup 1.0000x reference)
#include <cuda_runtime.h>
#include <cstdint>

#define IN_CH 16
#define OUT_CH 32
#define BATCH 8
#define H 32
#define W 32
#define NCP (IN_CH / 2)            // 8 channel pairs
#define NTAP 9

typedef unsigned long long ull;

__device__ __forceinline__ ull add2(ull a, ull b) {
    ull r; asm("add.rn.f32x2 %0, %1, %2;" : "=l"(r) : "l"(a), "l"(b)); return r;
}
__device__ __forceinline__ ull fma2(ull a, ull b, ull c) {
    ull r; asm("fma.rn.f32x2 %0, %1, %2, %3;" : "=l"(r) : "l"(a), "l"(b), "l"(c)); return r;
}
__device__ __forceinline__ ull pack2(float lo, float hi) {
    ull r;
    asm("mov.b64 %0, {%1, %2};" : "=l"(r)
        : "r"(__float_as_uint(lo)), "r"(__float_as_uint(hi)));
    return r;
}

// ---------------------------------------------------------------------------
// Single fused kernel, ONE WAVE, staged coef loads.
//   Grid 128 = (image b, row pair). Block 512 = 16 warps.
//   Warp w = (cp = w&7, half = w>>3). lane = output channel o.
//   Prologue:
//     1. tile slice prefetch (5 guarded LDG)
//     2. coef inputs staged through smem: warp's pos slice is CONTIGUOUS in
//        gmem -> lane-linear LDG.32 (1 line / 1 wavefront each, vs 3 for the
//        scattered per-triple gather), conflict-free LDS extraction
//        (bank 3*lane+c distinct), rcp issued between pos and val passes.
//     3. STS tile (pad-18), STS packed coef tables, STS v1 partials.
//   Main: warp = (cp, r0=half), coefs smem->regs, base folded into acc init,
//     cg loop unroll 2 (I$), only broadcast LDS.64 in-loop.
//   Epilogue: sum 8 cp-partials, transposed coalesced store.
// ---------------------------------------------------------------------------
#define TCOLS 34
#define TROWS 4
#define NCELL (TROWS * TCOLS)         // 136 cells
#define CELLF 18                      // floats per cell (2-way STS max)
#define CELL_ULL 9
#define TILE_FLOATS (NCELL * IN_CH)   // 2176 logical elements

#define OFF_CNP   0                   // 8*9*32 ull = 18432 B per table
#define OFF_CSM   18432
#define OFF_CDSH  36864
#define OFF_TILE  55296               // 136*18*4 = 9792 B
#define OFF_PART  65088               // 8*64*33*4 = 67584 B (also coef staging)
#define OFF_VSUM  132672              // 8*2*32*4 = 2048 B
#define SMEM_BYTES 134720

#define STAGE_WARP 960                // floats of staging per warp (<= part)

__global__ __launch_bounds__(512, 1)
void apc_fused(const float* __restrict__ x,
               const float* __restrict__ pos,
               const float* __restrict__ val,
               float* __restrict__ out) {
    extern __shared__ char sm_raw[];
    ull*   c_np    = (ull*)(sm_raw + OFF_CNP);
    ull*   c_sm    = (ull*)(sm_raw + OFF_CSM);
    ull*   c_dsh   = (ull*)(sm_raw + OFF_CDSH);
    float* sm_tile = (float*)(sm_raw + OFF_TILE);
    ull*   tile64  = (ull*)sm_tile;
    float* sm_part = (float*)(sm_raw + OFF_PART);
    float* sm_vs   = (float*)(sm_raw + OFF_VSUM);

    const int tid = threadIdx.x;
    const int b  = blockIdx.x >> 4;           // image
    const int y0 = (blockIdx.x & 15) << 1;    // first output row of pair
    const int w  = tid >> 5;
    const int o  = tid & 31;                  // lane = output channel
    const int cp   = w & 7;                   // channel pair
    const int half = w >> 3;                  // tap half / row of pair

    // ==== Prologue 1: prefetch tile slice into registers ====
    const float* xb = x + b * (IN_CH * H * W);
    float tv[5];
    #pragma unroll
    for (int k = 0; k < 5; k++) {
        int idx = tid + k * 512;
        float v = 0.f;
        if (idx < TILE_FLOATS) {
            int c   = idx / NCELL;            // channel outer: coalesced LDG
            int rem = idx - c * NCELL;
            int r   = rem / TCOLS;
            int col = rem - r * TCOLS;
            int gy = y0 + r - 1;
            int gx = col - 1;
            if ((unsigned)gy < (unsigned)H && (unsigned)gx < (unsigned)W)
                v = xb[(c * H + gy) * W + gx];
        }
        tv[k] = v;
    }

    // ==== Prologue 2: staged coef computation ====
    //   y_i(x) = v1 + sm*d + dsh*|d|, d = x - p1
    const int t0 = half ? 5 : 0;
    const int tn = half ? 4 : 5;
    const int nld = tn * 3;                   // lane-linear loads per hf
    float* stage = sm_part + w * STAGE_WARP;  // per-warp buffer (aliased)

    // stage pos: contiguous slice, 1-line LDG.32s
    #pragma unroll
    for (int hf = 0; hf < 2; hf++) {
        const float* src = pos + (((2 * cp + hf) * NTAP + t0) * 32) * 3;
        #pragma unroll
        for (int k = 0; k < 15; k++)
            if (k < nld) stage[hf * 480 + k * 32 + o] = src[k * 32 + o];
    }
    __syncwarp();

    // extract p's (conflict-free LDS), compute rcp terms (MUFU hidden by val)
    float np1v[10], rA[10], rB[10];
    #pragma unroll
    for (int hf = 0; hf < 2; hf++) {
        #pragma unroll
        for (int tt = 0; tt < 5; tt++)
            if (tt < tn) {
                int sb = hf * 480 + tt * 96 + 3 * o;
                float p0 = stage[sb], p1 = stage[sb + 1], p2 = stage[sb + 2];
                float A = p1 - p0, B = p2 - p1;
                float r = __fdividef(1.f, A * B);
                int u = hf * 5 + tt;
                np1v[u] = -p1;
                rA[u] = r * A;
                rB[u] = r * B;
            }
    }
    __syncwarp();

    // stage val over the same buffer
    #pragma unroll
    for (int hf = 0; hf < 2; hf++) {
        const float* src = val + (((2 * cp + hf) * NTAP + t0) * 32) * 3;
        #pragma unroll
        for (int k = 0; k < 15; k++)
            if (k < nld) stage[hf * 480 + k * 32 + o] = src[k * 32 + o];
    }
    __syncwarp();

    // extract v's, finish coefs, write packed tables
    {
        float vs = 0.f;
        #pragma unroll
        for (int tt = 0; tt < 5; tt++)
            if (tt < tn) {
                float smf[2], dsf[2];
                #pragma unroll
                for (int hf = 0; hf < 2; hf++) {
                    int sb = hf * 480 + tt * 96 + 3 * o;
                    float v0 = stage[sb], v1 = stage[sb + 1], v2 = stage[sb + 2];
                    int u = hf * 5 + tt;
                    float s0 = (v1 - v0) * rB[u];
                    float s1 = (v2 - v1) * rA[u];
                    smf[hf] = 0.5f * (s0 + s1);
                    dsf[hf] = 0.5f * (s1 - s0);
                    vs += v1;
                }
                int ci = (cp * NTAP + t0 + tt) * 32 + o;
                c_np [ci] = pack2(np1v[tt], np1v[5 + tt]);
                c_sm [ci] = pack2(smf[0], smf[1]);
                c_dsh[ci] = pack2(dsf[0], dsf[1]);
            }
        sm_vs[(cp * 2 + half) * 32 + o] = vs;
    }

    // ==== Prologue 3: store tile slice (pad-18 cells, 2-way STS max) ====
    #pragma unroll
    for (int k = 0; k < 5; k++) {
        int idx = tid + k * 512;
        if (idx < TILE_FLOATS) {
            int c   = idx / NCELL;
            int rem = idx - c * NCELL;
            sm_tile[rem * CELLF + c] = tv[k];
        }
    }
    __syncthreads();

    // ==== Main: warp = (cp, r0 = half). Coefs smem -> registers ====
    const int r0 = half;
    ull cnp[NTAP], csm[NTAP], cdsh[NTAP];
    {
        const ull* pn = c_np  + (cp * NTAP) * 32 + o;
        const ull* ps = c_sm  + (cp * NTAP) * 32 + o;
        const ull* pd = c_dsh + (cp * NTAP) * 32 + o;
        #pragma unroll
        for (int t = 0; t < NTAP; t++) {
            cnp[t]  = pn[t * 32];
            csm[t]  = ps[t * 32];
            cdsh[t] = pd[t * 32];
        }
    }
    // base term for this cp (both halves), folded into acc initialization
    const float vsall = sm_vs[(cp * 2) * 32 + o] + sm_vs[(cp * 2 + 1) * 32 + o];
    const ull accInit = pack2(vsall, 0.f);

    const ull ABS2 = 0x7FFFFFFF7FFFFFFFull;
    #pragma unroll 2
    for (int cg = 0; cg < 4; cg++) {
        const int c0 = cg << 3;
        ull acc[8];
        #pragma unroll
        for (int p = 0; p < 8; p++) acc[p] = accInit;

        #pragma unroll
        for (int kh = 0; kh < 3; kh++) {
            // window row r0+kh: 10 pair-values, warp-uniform broadcast LDS.64
            ull xr[10];
            #pragma unroll
            for (int m = 0; m < 10; m++)
                xr[m] = tile64[((r0 + kh) * TCOLS + c0 + m) * CELL_ULL + cp];

            #pragma unroll
            for (int kw = 0; kw < 3; kw++) {
                const int t = kh * 3 + kw;
                const ull np1 = cnp[t];
                const ull smv = csm[t];
                const ull dsh = cdsh[t];
                #pragma unroll
                for (int p = 0; p < 8; p++) {
                    ull d = add2(xr[p + kw], np1);
                    ull a = d & ABS2;
                    acc[p] = fma2(smv, d, acc[p]);
                    acc[p] = fma2(dsh, a, acc[p]);
                }
            }
        }

        // horizontal pair reduce -> padded smem partials (lanes contiguous)
        #pragma unroll
        for (int p = 0; p < 8; p++) {
            float lo = __uint_as_float((unsigned)acc[p]);
            float hi = __uint_as_float((unsigned)(acc[p] >> 32));
            sm_part[(cp * 64 + (r0 << 5) + c0 + p) * 33 + o] = lo + hi;
        }
    }
    __syncthreads();

    // ==== Epilogue: sum 8 cp-partials; transposed coalesced store ====
    #pragma unroll
    for (int k = 0; k < 4; k++) {
        int q  = tid + k * 512;       // (oo = q>>6 warp-uniform, px = q&63)
        int oo = q >> 6;
        int px = q & 63;
        float s = 0.f;
        #pragma unroll
        for (int g = 0; g < NCP; g++)
            s += sm_part[(g * 64 + px) * 33 + oo];  // stride-33: conflict-free
        int r = px >> 5, col = px & 31;
        out[((b * OUT_CH + oo) * H + (y0 + r)) * W + col] = s;
    }
}

extern "C" void kernel_launch(void* const* d_in, const int* in_sizes, int n_in,
                              void* d_out, int out_size) {
    const float* x   = (const float*)d_in[0];
    const float* pos = (const float*)d_in[1];
    const float* val = (const float*)d_in[2];
    float* out = (float*)d_out;

    cudaFuncSetAttribute(apc_fused, cudaFuncAttributeMaxDynamicSharedMemorySize,
                         SMEM_BYTES);
    apc_fused<<<BATCH * (H / 2), 512, SMEM_BYTES>>>(x, pos, val, out);
}

// round 16
// speedup vs baseline: 1.1597x; 1.1597x over previous
#include <cuda_runtime.h>
#include <cstdint>

#define IN_CH 16
#define OUT_CH 32
#define BATCH 8
#define H 32
#define W 32
#define NCP (IN_CH / 2)            // 8 channel pairs
#define NTAP 9

typedef unsigned long long ull;

__device__ __forceinline__ ull add2(ull a, ull b) {
    ull r; asm("add.rn.f32x2 %0, %1, %2;" : "=l"(r) : "l"(a), "l"(b)); return r;
}
__device__ __forceinline__ ull fma2(ull a, ull b, ull c) {
    ull r; asm("fma.rn.f32x2 %0, %1, %2, %3;" : "=l"(r) : "l"(a), "l"(b), "l"(c)); return r;
}
__device__ __forceinline__ ull pack2(float lo, float hi) {
    ull r;
    asm("mov.b64 %0, {%1, %2};" : "=l"(r)
        : "r"(__float_as_uint(lo)), "r"(__float_as_uint(hi)));
    return r;
}

// ---------------------------------------------------------------------------
// Single fused kernel, ONE WAVE (R12 structure, shift-only staging).
//   y_i(x) = v1 + sm*d + dsh*|d|, d = x - p1, sm=(s0+s1)/2, dsh=(s1-s0)/2
//   Grid 128 = (image b, row pair y0..y0+1). Block 512 = 16 warps.
//   Warp w = (cp = w&7, half = w>>3). lane = output channel o.
//   Prologue (every warp, one MLP hump):
//     1. main-region tile prefetch: 2048 = 4x512 elems, PURE SHIFT indexing
//        (halo cols gx=-1,32 are always zero -> zeroed separately by t<128)
//     2. coef LDGs + compute for taps [half] (single-rcp trick)
//     3. STS tile (pad-18 cells, 2-way max), coef tables, v1 partials
//   Main: warp = (cp, r0=half): coefs smem->regs, base folded into acc init;
//     4 col-groups x 8 px, group = add2 + 2xLOP3 + 2xfma2, only broadcast
//     LDS.64 in-loop.
//   Epilogue: sum 8 cp-partials, transposed coalesced store.
// ---------------------------------------------------------------------------
#define TCOLS 34
#define TROWS 4
#define CELLF 18                      // floats per cell (pad: 2-way STS max)
#define CELL_ULL 9

#define OFF_CNP   0                   // 8*9*32 ull = 18432 B per table
#define OFF_CSM   18432
#define OFF_CDSH  36864
#define OFF_TILE  55296               // 136*18*4 = 9792 B
#define OFF_PART  65088               // 8*64*33*4 = 67584 B
#define OFF_VSUM  132672              // 8*2*32*4 = 2048 B
#define SMEM_BYTES 134720

__global__ __launch_bounds__(512)
void apc_fused(const float* __restrict__ x,
               const float* __restrict__ pos,
               const float* __restrict__ val,
               float* __restrict__ out) {
    extern __shared__ char sm_raw[];
    ull*   c_np    = (ull*)(sm_raw + OFF_CNP);
    ull*   c_sm    = (ull*)(sm_raw + OFF_CSM);
    ull*   c_dsh   = (ull*)(sm_raw + OFF_CDSH);
    float* sm_tile = (float*)(sm_raw + OFF_TILE);
    ull*   tile64  = (ull*)sm_tile;
    float* sm_part = (float*)(sm_raw + OFF_PART);
    float* sm_vs   = (float*)(sm_raw + OFF_VSUM);

    const int tid = threadIdx.x;
    const int b  = blockIdx.x >> 4;           // image
    const int y0 = (blockIdx.x & 15) << 1;    // first output row of pair
    const int w  = tid >> 5;
    const int o  = tid & 31;                  // lane = output channel
    const int cp   = w & 7;                   // channel pair
    const int half = w >> 3;                  // tap half / row of pair

    // ==== Prologue 1: main-region tile prefetch, shift-only indexing ====
    // element idx = k*512 + tid, 0..2047: c = idx>>7, r = (idx>>5)&3,
    // col = idx&31 -> tile cell (r*34 + col + 1); only gy needs a guard.
    const float* xb = x + b * (IN_CH * H * W);
    float tv[4];
    #pragma unroll
    for (int k = 0; k < 4; k++) {
        int idx = tid + k * 512;
        int c   = idx >> 7;
        int r   = (idx >> 5) & 3;
        int col = idx & 31;
        int gy = y0 + r - 1;
        float v = 0.f;
        if ((unsigned)gy < (unsigned)H)
            v = xb[(c * H + gy) * W + col];
        tv[k] = v;
    }

    // ==== Prologue 2: coefs for taps [t0, t0+tn), both channels ====
    {
        const int t0 = half ? 5 : 0;
        const int tn = half ? 4 : 5;
        float vs = 0.f;
        #pragma unroll
        for (int tt = 0; tt < 5; tt++) {
            if (tt < tn) {
                const int t = t0 + tt;
                float npf[2], smf[2], dsf[2];
                #pragma unroll
                for (int hf = 0; hf < 2; hf++) {
                    int i = (2 * cp + hf) * NTAP + t;
                    int base = (i * 32 + o) * 3;
                    float p0 = pos[base], p1 = pos[base + 1], p2 = pos[base + 2];
                    float v0 = val[base], v1 = val[base + 1], v2 = val[base + 2];
                    float A = p1 - p0, B = p2 - p1;
                    float r = __fdividef(1.f, A * B);   // 1 MUFU per triple
                    float s0 = (v1 - v0) * r * B;
                    float s1 = (v2 - v1) * r * A;
                    npf[hf] = -p1;
                    smf[hf] = 0.5f * (s0 + s1);
                    dsf[hf] = 0.5f * (s1 - s0);
                    vs += v1;
                }
                int ci = (cp * NTAP + t) * 32 + o;
                c_np [ci] = pack2(npf[0], npf[1]);
                c_sm [ci] = pack2(smf[0], smf[1]);
                c_dsh[ci] = pack2(dsf[0], dsf[1]);
            }
        }
        sm_vs[(cp * 2 + half) * 32 + o] = vs;
    }

    // ==== Prologue 3: STS tile. Halo cols are constant zero. ====
    if (tid < 128) {
        // 4 rows x 2 halo cols x 16 ch: c = tid>>3, r = (tid>>1)&3, side = tid&1
        int c = tid >> 3;
        int r = (tid >> 1) & 3;
        int cell = r * TCOLS + ((tid & 1) ? 33 : 0);
        sm_tile[cell * CELLF + c] = 0.f;
    }
    #pragma unroll
    for (int k = 0; k < 4; k++) {
        int idx = tid + k * 512;
        int c   = idx >> 7;
        int r   = (idx >> 5) & 3;
        int col = idx & 31;
        sm_tile[(r * TCOLS + col + 1) * CELLF + c] = tv[k];
    }
    __syncthreads();

    // ==== Main: warp = (cp, r0 = half). Coefs smem -> registers ====
    const int r0 = half;
    ull cnp[NTAP], csm[NTAP], cdsh[NTAP];
    {
        const ull* pn = c_np  + (cp * NTAP) * 32 + o;
        const ull* ps = c_sm  + (cp * NTAP) * 32 + o;
        const ull* pd = c_dsh + (cp * NTAP) * 32 + o;
        #pragma unroll
        for (int t = 0; t < NTAP; t++) {
            cnp[t]  = pn[t * 32];
            csm[t]  = ps[t * 32];
            cdsh[t] = pd[t * 32];
        }
    }
    // base term for this cp (both halves), folded into acc initialization
    const float vsall = sm_vs[(cp * 2) * 32 + o] + sm_vs[(cp * 2 + 1) * 32 + o];
    const ull accInit = pack2(vsall, 0.f);

    const ull ABS2 = 0x7FFFFFFF7FFFFFFFull;
    #pragma unroll
    for (int cg = 0; cg < 4; cg++) {
        const int c0 = cg << 3;
        ull acc[8];
        #pragma unroll
        for (int p = 0; p < 8; p++) acc[p] = accInit;

        #pragma unroll
        for (int kh = 0; kh < 3; kh++) {
            // window row r0+kh: 10 pair-values, warp-uniform broadcast LDS.64
            ull xr[10];
            #pragma unroll
            for (int m = 0; m < 10; m++)
                xr[m] = tile64[((r0 + kh) * TCOLS + c0 + m) * CELL_ULL + cp];

            #pragma unroll
            for (int kw = 0; kw < 3; kw++) {
                const int t = kh * 3 + kw;
                const ull np1 = cnp[t];
                const ull smv = csm[t];
                const ull dsh = cdsh[t];
                #pragma unroll
                for (int p = 0; p < 8; p++) {
                    ull d = add2(xr[p + kw], np1);
                    ull a = d & ABS2;
                    acc[p] = fma2(smv, d, acc[p]);
                    acc[p] = fma2(dsh, a, acc[p]);
                }
            }
        }

        // horizontal pair reduce -> padded smem partials (lanes contiguous)
        #pragma unroll
        for (int p = 0; p < 8; p++) {
            float lo = __uint_as_float((unsigned)acc[p]);
            float hi = __uint_as_float((unsigned)(acc[p] >> 32));
            sm_part[(cp * 64 + (r0 << 5) + c0 + p) * 33 + o] = lo + hi;
        }
    }
    __syncthreads();

    // ==== Epilogue: sum 8 cp-partials; transposed coalesced store ====
    #pragma unroll
    for (int k = 0; k < 4; k++) {
        int q  = tid + k * 512;       // (oo = q>>6 warp-uniform, px = q&63)
        int oo = q >> 6;
        int px = q & 63;
        float s = 0.f;
        #pragma unroll
        for (int g = 0; g < NCP; g++)
            s += sm_part[(g * 64 + px) * 33 + oo];  // stride-33: conflict-free
        int r = px >> 5, col = px & 31;
        out[((b * OUT_CH + oo) * H + (y0 + r)) * W + col] = s;
    }
}

extern "C" void kernel_launch(void* const* d_in, const int* in_sizes, int n_in,
                              void* d_out, int out_size) {
    const float* x   = (const float*)d_in[0];
    const float* pos = (const float*)d_in[1];
    const float* val = (const float*)d_in[2];
    float* out = (float*)d_out;

    cudaFuncSetAttribute(apc_fused, cudaFuncAttributeMaxDynamicSharedMemorySize,
                         SMEM_BYTES);
    apc_fused<<<BATCH * (H / 2), 512, SMEM_BYTES>>>(x, pos, val, out);
}

// round 17
// speedup vs baseline: 1.1859x; 1.0226x over previous
#include <cuda_runtime.h>
#include <cstdint>

#define IN_CH 16
#define OUT_CH 32
#define BATCH 8
#define H 32
#define W 32
#define NCP (IN_CH / 2)            // 8 channel pairs
#define NTAP 9

typedef unsigned long long ull;

__device__ __forceinline__ ull add2(ull a, ull b) {
    ull r; asm("add.rn.f32x2 %0, %1, %2;" : "=l"(r) : "l"(a), "l"(b)); return r;
}
__device__ __forceinline__ ull fma2(ull a, ull b, ull c) {
    ull r; asm("fma.rn.f32x2 %0, %1, %2, %3;" : "=l"(r) : "l"(a), "l"(b), "l"(c)); return r;
}
__device__ __forceinline__ ull pack2(float lo, float hi) {
    ull r;
    asm("mov.b64 %0, {%1, %2};" : "=l"(r)
        : "r"(__float_as_uint(lo)), "r"(__float_as_uint(hi)));
    return r;
}

// ---------------------------------------------------------------------------
// Single fused kernel, TWO CO-RESIDENT BLOCKS PER SM.
//   y_i(x) = v1 + sm*d + dsh*|d|, d = x - p1, sm=(s0+s1)/2, dsh=(s1-s0)/2
//   Grid 256 = (image b, row y). Block 256 = 8 warps. Warp = channel pair cp,
//   lane = output channel o. smem 97.5 KB -> 2 blocks/SM: unsynchronized
//   sibling block fills this block's barrier/latency stalls.
//   Prologue: tile prefetch (shift-only indexing, halo zeroed separately) +
//     full 9-tap coef compute per warp (single-rcp trick) -> packed tables.
//   Main: coefs smem->regs (27 LDS.64 once), base folded into acc init;
//     4 col-groups x 8 px, group = add2 + 2xLOP3 + 2xfma2, only broadcast
//     LDS.64 in-loop.
//   Epilogue: sum 8 cp-partials, transposed coalesced store.
// ---------------------------------------------------------------------------
#define TCOLS 34
#define CELLF 18                      // floats per cell (pad: 2-way STS max)
#define CELL_ULL 9

#define OFF_CNP   0                   // 8*9*32 ull = 18432 B per table
#define OFF_CSM   18432
#define OFF_CDSH  36864
#define OFF_TILE  55296               // 3*34*18*4 = 7344 B
#define OFF_PART  62640               // 8*32*33*4 = 33792 B
#define OFF_VSUM  96432               // 8*32*4 = 1024 B
#define SMEM_BYTES 97456              // x2 = 195 KB <= 228 KB/SM

__global__ __launch_bounds__(256, 2)
void apc_fused(const float* __restrict__ x,
               const float* __restrict__ pos,
               const float* __restrict__ val,
               float* __restrict__ out) {
    extern __shared__ char sm_raw[];
    ull*   c_np    = (ull*)(sm_raw + OFF_CNP);
    ull*   c_sm    = (ull*)(sm_raw + OFF_CSM);
    ull*   c_dsh   = (ull*)(sm_raw + OFF_CDSH);
    float* sm_tile = (float*)(sm_raw + OFF_TILE);
    ull*   tile64  = (ull*)sm_tile;
    float* sm_part = (float*)(sm_raw + OFF_PART);
    float* sm_vs   = (float*)(sm_raw + OFF_VSUM);

    const int tid = threadIdx.x;
    const int b = blockIdx.x >> 5;            // image
    const int y = blockIdx.x & 31;            // output row
    const int cp = tid >> 5;                  // warp = channel pair
    const int o  = tid & 31;                  // lane = output channel

    // ==== Prologue 1: tile prefetch, shift-only indexing ====
    // rows y-1..y+1 x 32 cols x 16 ch = 1536 = 3 x (2 x 256) elements
    const float* xb = x + b * (IN_CH * H * W);
    float tv[3][2];
    #pragma unroll
    for (int r = 0; r < 3; r++) {
        int gy = y + r - 1;
        #pragma unroll
        for (int k = 0; k < 2; k++) {
            int idx = tid + k * 256;
            int c   = idx >> 5;               // 0..15
            int col = idx & 31;
            float v = 0.f;
            if ((unsigned)gy < (unsigned)H)
                v = xb[(c * H + gy) * W + col];
            tv[r][k] = v;
        }
    }

    // ==== Prologue 2: coefs, full 9 taps x 2 channels per warp ====
    {
        float vs = 0.f;
        #pragma unroll
        for (int t = 0; t < NTAP; t++) {
            float npf[2], smf[2], dsf[2];
            #pragma unroll
            for (int hf = 0; hf < 2; hf++) {
                int i = (2 * cp + hf) * NTAP + t;
                int base = (i * 32 + o) * 3;
                float p0 = pos[base], p1 = pos[base + 1], p2 = pos[base + 2];
                float v0 = val[base], v1 = val[base + 1], v2 = val[base + 2];
                float A = p1 - p0, B = p2 - p1;
                float r = __fdividef(1.f, A * B);   // 1 MUFU per triple
                float s0 = (v1 - v0) * r * B;
                float s1 = (v2 - v1) * r * A;
                npf[hf] = -p1;
                smf[hf] = 0.5f * (s0 + s1);
                dsf[hf] = 0.5f * (s1 - s0);
                vs += v1;
            }
            int ci = (cp * NTAP + t) * 32 + o;
            c_np [ci] = pack2(npf[0], npf[1]);
            c_sm [ci] = pack2(smf[0], smf[1]);
            c_dsh[ci] = pack2(dsf[0], dsf[1]);
        }
        sm_vs[cp * 32 + o] = vs;
    }

    // ==== Prologue 3: STS tile (halo cols are constant zero) ====
    if (tid < 96) {
        // 3 rows x 2 halo cols x 16 ch
        int c  = tid & 15;
        int rs = tid >> 4;                    // 0..5
        int r  = rs >> 1;
        int cell = r * TCOLS + ((rs & 1) ? 33 : 0);
        sm_tile[cell * CELLF + c] = 0.f;
    }
    #pragma unroll
    for (int r = 0; r < 3; r++)
        #pragma unroll
        for (int k = 0; k < 2; k++) {
            int idx = tid + k * 256;
            int c   = idx >> 5;
            int col = idx & 31;
            sm_tile[(r * TCOLS + col + 1) * CELLF + c] = tv[r][k];
        }
    __syncthreads();

    // ==== Main: coefs smem -> registers, then pipe-floor loop ====
    ull cnp[NTAP], csm[NTAP], cdsh[NTAP];
    {
        const ull* pn = c_np  + (cp * NTAP) * 32 + o;
        const ull* ps = c_sm  + (cp * NTAP) * 32 + o;
        const ull* pd = c_dsh + (cp * NTAP) * 32 + o;
        #pragma unroll
        for (int t = 0; t < NTAP; t++) {
            cnp[t]  = pn[t * 32];
            csm[t]  = ps[t * 32];
            cdsh[t] = pd[t * 32];
        }
    }
    // base term (this cp's sum of v1), folded into acc initialization
    const ull accInit = pack2(sm_vs[cp * 32 + o], 0.f);

    const ull ABS2 = 0x7FFFFFFF7FFFFFFFull;
    #pragma unroll
    for (int cg = 0; cg < 4; cg++) {
        const int c0 = cg << 3;
        ull acc[8];
        #pragma unroll
        for (int p = 0; p < 8; p++) acc[p] = accInit;

        #pragma unroll
        for (int kh = 0; kh < 3; kh++) {
            // window row kh: 10 pair-values, warp-uniform broadcast LDS.64
            ull xr[10];
            #pragma unroll
            for (int m = 0; m < 10; m++)
                xr[m] = tile64[(kh * TCOLS + c0 + m) * CELL_ULL + cp];

            #pragma unroll
            for (int kw = 0; kw < 3; kw++) {
                const int t = kh * 3 + kw;
                const ull np1 = cnp[t];
                const ull smv = csm[t];
                const ull dsh = cdsh[t];
                #pragma unroll
                for (int p = 0; p < 8; p++) {
                    ull d = add2(xr[p + kw], np1);
                    ull a = d & ABS2;
                    acc[p] = fma2(smv, d, acc[p]);
                    acc[p] = fma2(dsh, a, acc[p]);
                }
            }
        }

        // horizontal pair reduce -> padded smem partials (lanes contiguous)
        #pragma unroll
        for (int p = 0; p < 8; p++) {
            float lo = __uint_as_float((unsigned)acc[p]);
            float hi = __uint_as_float((unsigned)(acc[p] >> 32));
            sm_part[(cp * 32 + c0 + p) * 33 + o] = lo + hi;
        }
    }
    __syncthreads();

    // ==== Epilogue: sum 8 cp-partials; transposed coalesced store ====
    #pragma unroll
    for (int k = 0; k < 4; k++) {
        int q  = tid + k * 256;       // (oo = q>>5 warp-uniform, px = q&31)
        int oo = q >> 5;
        int px = q & 31;
        float s = 0.f;
        #pragma unroll
        for (int g = 0; g < NCP; g++)
            s += sm_part[(g * 32 + px) * 33 + oo];  // stride-33: conflict-free
        out[((b * OUT_CH + oo) * H + y) * W + px] = s;
    }
}

extern "C" void kernel_launch(void* const* d_in, const int* in_sizes, int n_in,
                              void* d_out, int out_size) {
    const float* x   = (const float*)d_in[0];
    const float* pos = (const float*)d_in[1];
    const float* val = (const float*)d_in[2];
    float* out = (float*)d_out;

    cudaFuncSetAttribute(apc_fused, cudaFuncAttributeMaxDynamicSharedMemorySize,
                         SMEM_BYTES);
    apc_fused<<<BATCH * H, 256, SMEM_BYTES>>>(x, pos, val, out);
}